// round 2
// baseline (speedup 1.0000x reference)
#include <cuda_runtime.h>
#include <math.h>

#define NN 50000
#define EE 800000
#define FF 256

// ---------------- device scratch (no runtime allocation allowed) ------------
__device__ int   g_is64;
__device__ int   g_cnt[NN];
__device__ int   g_cursor[NN];
__device__ int   g_rowstart[NN + 1];
__device__ float g_dis[NN];
__device__ int   g_esrc[EE];
__device__ float g_enorm[EE];
__device__ float g_T [(size_t)NN * FF];
__device__ float g_HA[(size_t)NN * FF];
__device__ float g_HB[(size_t)NN * FF];
__device__ float g_t2[NN * 2];

// ---------------- small helpers ---------------------------------------------
__device__ __forceinline__ int load_edge(const void* ei, long long idx) {
    if (g_is64) return (int)((const long long*)ei)[idx];
    return ((const int*)ei)[idx];
}

// Detect int64 vs int32 edge_index: for int64 (values < 2^31), every odd
// 32-bit word is the zero high-half. For int32 real data the odds of 32
// consecutive odd words being zero are ~(1/50000)^32.
__global__ void k_detect(const int* p) {
    if (threadIdx.x == 0) {
        int any = 0;
        #pragma unroll
        for (int i = 1; i < 64; i += 2) any |= p[i];
        g_is64 = (any == 0) ? 1 : 0;
    }
}

__global__ void k_init_counts() {
    int i = blockIdx.x * blockDim.x + threadIdx.x;
    if (i < NN) { g_cnt[i] = 0; g_cursor[i] = 0; }
}

__global__ void k_count(const void* ei) {
    int e = blockIdx.x * blockDim.x + threadIdx.x;
    if (e >= EE) return;
    int dst = load_edge(ei, (long long)EE + e);
    atomicAdd(&g_cnt[dst], 1);
}

__global__ void k_dis() {
    int i = blockIdx.x * blockDim.x + threadIdx.x;
    if (i < NN) g_dis[i] = rsqrtf((float)(g_cnt[i] + 1));  // +1 self-loop
}

// Single-block exclusive scan of g_cnt -> g_rowstart (50001 entries).
__global__ void k_scan() {
    __shared__ int sh[1024];
    __shared__ int s_running;
    int tid = threadIdx.x;
    if (tid == 0) s_running = 0;
    __syncthreads();
    for (int base = 0; base < NN; base += 1024) {
        int i = base + tid;
        int v = (i < NN) ? g_cnt[i] : 0;
        sh[tid] = v;
        __syncthreads();
        for (int off = 1; off < 1024; off <<= 1) {
            int t = (tid >= off) ? sh[tid - off] : 0;
            __syncthreads();
            sh[tid] += t;
            __syncthreads();
        }
        int incl = sh[tid];
        if (i < NN) g_rowstart[i] = s_running + incl - v;  // exclusive
        __syncthreads();
        if (tid == 1023) s_running += incl;               // chunk total
        __syncthreads();
    }
    if (tid == 0) g_rowstart[NN] = s_running;
}

// Bucket edges by destination (CSR). Also precompute per-edge norm.
__global__ void k_build(const void* ei) {
    int e = blockIdx.x * blockDim.x + threadIdx.x;
    if (e >= EE) return;
    int src = load_edge(ei, e);
    int dst = load_edge(ei, (long long)EE + e);
    float w = g_dis[src] * g_dis[dst];
    int pos = g_rowstart[dst] + atomicAdd(&g_cursor[dst], 1);
    g_esrc[pos]  = src;
    g_enorm[pos] = w;
}

// ---------------- dense GEMM: C[N,256] = (relu?)A[N,256] @ W[256,256] --------
#define BM 128
#define BN 128
#define BK 16

template <bool RELU>
__global__ __launch_bounds__(256, 2) void k_gemm(const float* __restrict__ A,
                                                 const float* __restrict__ Wm,
                                                 float* __restrict__ C,
                                                 int nrows) {
    __shared__ float As[BK][BM];
    __shared__ float Bs[BK][BN];
    int tid = threadIdx.x;
    int rowBase = blockIdx.x * BM;
    int colBase = blockIdx.y * BN;
    int tx = tid & 15;
    int ty = tid >> 4;

    float acc[8][8];
    #pragma unroll
    for (int i = 0; i < 8; i++)
        #pragma unroll
        for (int j = 0; j < 8; j++) acc[i][j] = 0.f;

    for (int k0 = 0; k0 < 256; k0 += BK) {
        // A tile: 128x16 -> As[k][row] (transposed store), relu fused on load
        #pragma unroll
        for (int l = 0; l < 2; l++) {
            int id = tid + l * 256;
            int r  = id >> 2;
            int q  = id & 3;
            int row = rowBase + r;
            float4 v = make_float4(0.f, 0.f, 0.f, 0.f);
            if (row < nrows)
                v = *(const float4*)(A + (size_t)row * 256 + k0 + q * 4);
            if (RELU) {
                v.x = fmaxf(v.x, 0.f); v.y = fmaxf(v.y, 0.f);
                v.z = fmaxf(v.z, 0.f); v.w = fmaxf(v.w, 0.f);
            }
            As[q * 4 + 0][r] = v.x;
            As[q * 4 + 1][r] = v.y;
            As[q * 4 + 2][r] = v.z;
            As[q * 4 + 3][r] = v.w;
        }
        // B tile: 16x128, direct
        #pragma unroll
        for (int l = 0; l < 2; l++) {
            int id = tid + l * 256;
            int kk = id >> 5;
            int c4 = id & 31;
            float4 v = *(const float4*)(Wm + (size_t)(k0 + kk) * 256 + colBase + c4 * 4);
            *(float4*)&Bs[kk][c4 * 4] = v;
        }
        __syncthreads();

        #pragma unroll
        for (int kk = 0; kk < BK; kk++) {
            float a[8], b[8];
            *(float4*)&a[0] = *(const float4*)&As[kk][ty * 8];
            *(float4*)&a[4] = *(const float4*)&As[kk][ty * 8 + 4];
            *(float4*)&b[0] = *(const float4*)&Bs[kk][tx * 8];
            *(float4*)&b[4] = *(const float4*)&Bs[kk][tx * 8 + 4];
            #pragma unroll
            for (int i = 0; i < 8; i++)
                #pragma unroll
                for (int j = 0; j < 8; j++)
                    acc[i][j] = fmaf(a[i], b[j], acc[i][j]);
        }
        __syncthreads();
    }

    #pragma unroll
    for (int i = 0; i < 8; i++) {
        int row = rowBase + ty * 8 + i;
        if (row < nrows) {
            float4 v0 = make_float4(acc[i][0], acc[i][1], acc[i][2], acc[i][3]);
            float4 v1 = make_float4(acc[i][4], acc[i][5], acc[i][6], acc[i][7]);
            float* cp = C + (size_t)row * 256 + colBase + tx * 8;
            *(float4*)cp       = v0;
            *(float4*)(cp + 4) = v1;
        }
    }
}

// ---------------- aggregation, F=256: warp per node, CSR, no atomics --------
__global__ void k_agg(const float4* __restrict__ T4,
                      const float*  __restrict__ bias,
                      float4* __restrict__ O4) {
    int warp = (blockIdx.x * blockDim.x + threadIdx.x) >> 5;
    int lane = threadIdx.x & 31;
    if (warp >= NN) return;
    int node = warp;

    float ws = g_dis[node];
    ws *= ws;  // self-loop weight dis^2 = 1/deg

    float4 a0 = T4[(size_t)node * 64 + lane];
    float4 a1 = T4[(size_t)node * 64 + lane + 32];
    float4 acc0 = make_float4(a0.x * ws, a0.y * ws, a0.z * ws, a0.w * ws);
    float4 acc1 = make_float4(a1.x * ws, a1.y * ws, a1.z * ws, a1.w * ws);

    int p0 = g_rowstart[node];
    int p1 = g_rowstart[node + 1];
    for (int p = p0; p < p1; p++) {
        int   s = g_esrc[p];
        float w = g_enorm[p];
        float4 v0 = T4[(size_t)s * 64 + lane];
        float4 v1 = T4[(size_t)s * 64 + lane + 32];
        acc0.x = fmaf(v0.x, w, acc0.x); acc0.y = fmaf(v0.y, w, acc0.y);
        acc0.z = fmaf(v0.z, w, acc0.z); acc0.w = fmaf(v0.w, w, acc0.w);
        acc1.x = fmaf(v1.x, w, acc1.x); acc1.y = fmaf(v1.y, w, acc1.y);
        acc1.z = fmaf(v1.z, w, acc1.z); acc1.w = fmaf(v1.w, w, acc1.w);
    }

    float4 b0 = ((const float4*)bias)[lane];
    float4 b1 = ((const float4*)bias)[lane + 32];
    acc0.x += b0.x; acc0.y += b0.y; acc0.z += b0.z; acc0.w += b0.w;
    acc1.x += b1.x; acc1.y += b1.y; acc1.z += b1.z; acc1.w += b1.w;
    O4[(size_t)node * 64 + lane]      = acc0;
    O4[(size_t)node * 64 + lane + 32] = acc1;
}

// ---------------- last layer: t2[N,2] = relu(A) @ W3[256,2] ------------------
__global__ void k_gemm2(const float* __restrict__ A,
                        const float* __restrict__ W3,
                        float* __restrict__ t2) {
    int warp = (blockIdx.x * blockDim.x + threadIdx.x) >> 5;
    int lane = threadIdx.x & 31;
    if (warp >= NN) return;
    const float* row = A + (size_t)warp * 256;
    float s0 = 0.f, s1 = 0.f;
    #pragma unroll
    for (int k = lane; k < 256; k += 32) {
        float h = fmaxf(row[k], 0.f);
        float2 w = ((const float2*)W3)[k];
        s0 = fmaf(h, w.x, s0);
        s1 = fmaf(h, w.y, s1);
    }
    #pragma unroll
    for (int off = 16; off; off >>= 1) {
        s0 += __shfl_xor_sync(0xffffffffu, s0, off);
        s1 += __shfl_xor_sync(0xffffffffu, s1, off);
    }
    if (lane == 0) { t2[warp * 2] = s0; t2[warp * 2 + 1] = s1; }
}

// ---------------- final aggregation (F=2) into d_out -------------------------
__global__ void k_agg2(const float* __restrict__ t2,
                       const float* __restrict__ b3,
                       float* __restrict__ out) {
    int warp = (blockIdx.x * blockDim.x + threadIdx.x) >> 5;
    int lane = threadIdx.x & 31;
    if (warp >= NN) return;
    int node = warp;
    int p0 = g_rowstart[node];
    int p1 = g_rowstart[node + 1];
    float s0 = 0.f, s1 = 0.f;
    for (int p = p0 + lane; p < p1; p += 32) {
        int   s = g_esrc[p];
        float w = g_enorm[p];
        s0 = fmaf(t2[s * 2],     w, s0);
        s1 = fmaf(t2[s * 2 + 1], w, s1);
    }
    #pragma unroll
    for (int off = 16; off; off >>= 1) {
        s0 += __shfl_xor_sync(0xffffffffu, s0, off);
        s1 += __shfl_xor_sync(0xffffffffu, s1, off);
    }
    if (lane == 0) {
        float ws = g_dis[node];
        ws *= ws;
        out[node * 2]     = s0 + t2[node * 2]     * ws + b3[0];
        out[node * 2 + 1] = s1 + t2[node * 2 + 1] * ws + b3[1];
    }
}

// ---------------- launch ------------------------------------------------------
extern "C" void kernel_launch(void* const* d_in, const int* in_sizes, int n_in,
                              void* d_out, int out_size) {
    const float* x  = (const float*)d_in[0];
    const void*  ei = d_in[1];
    const float* W0 = (const float*)d_in[2];
    const float* b0 = (const float*)d_in[3];
    const float* W1 = (const float*)d_in[4];
    const float* b1 = (const float*)d_in[5];
    const float* W2 = (const float*)d_in[6];
    const float* b2 = (const float*)d_in[7];
    const float* W3 = (const float*)d_in[8];
    const float* b3 = (const float*)d_in[9];
    float* out = (float*)d_out;

    float *T, *HA, *HB, *t2;
    cudaGetSymbolAddress((void**)&T,  g_T);
    cudaGetSymbolAddress((void**)&HA, g_HA);
    cudaGetSymbolAddress((void**)&HB, g_HB);
    cudaGetSymbolAddress((void**)&t2, g_t2);

    const int nodeBlocks = (NN + 255) / 256;       // 196
    const int edgeBlocks = (EE + 255) / 256;       // 3125
    const int warpBlocks = (NN + 7) / 8;           // 6250 (8 warps / 256-thr block)
    dim3 gemmGrid((NN + BM - 1) / BM, 256 / BN);   // (391, 2)

    // ---- graph preprocessing (replayed every call; cheap) ----
    k_detect<<<1, 32>>>((const int*)ei);
    k_init_counts<<<nodeBlocks, 256>>>();
    k_count<<<edgeBlocks, 256>>>(ei);
    k_dis<<<nodeBlocks, 256>>>();
    k_scan<<<1, 1024>>>();
    k_build<<<edgeBlocks, 256>>>(ei);

    // ---- layer 1: x @ W0 -> T ; aggregate+bias -> HA (relu deferred) ----
    k_gemm<false><<<gemmGrid, 256>>>(x, W0, T, NN);
    k_agg<<<warpBlocks, 256>>>((const float4*)T, b0, (float4*)HA);

    // ---- layer 2 ----
    k_gemm<true><<<gemmGrid, 256>>>(HA, W1, T, NN);
    k_agg<<<warpBlocks, 256>>>((const float4*)T, b1, (float4*)HB);

    // ---- layer 3 ----
    k_gemm<true><<<gemmGrid, 256>>>(HB, W2, T, NN);
    k_agg<<<warpBlocks, 256>>>((const float4*)T, b2, (float4*)HA);

    // ---- layer 4: relu(HA) @ W3 -> t2 ; aggregate F=2 -> out ----
    k_gemm2<<<warpBlocks, 256>>>(HA, W3, t2);
    k_agg2<<<warpBlocks, 256>>>(t2, b3, out);
}